// round 2
// baseline (speedup 1.0000x reference)
#include <cuda_runtime.h>
#include <cuda_bf16.h>

// Problem constants (fixed shapes for this problem instance)
#define NMAX 100000
#define EMAX 6400000
#define HID  256
#define OUT  64
#define NT   32      // nodes per MLP tile

// Scratch (device globals: no allocation allowed in kernel_launch)
// xl padded to stride 4 for float4 gathers; h1 stride 12; h2 stride 28 (16B-aligned rows)
__device__ float g_xl[NMAX * 4];
__device__ float g_h1[NMAX * 12];
__device__ float g_h2[NMAX * 28];

// ---------------------------------------------------------------------------
// Vectorized no-return global atomic add (sm_90+)
// ---------------------------------------------------------------------------
__device__ __forceinline__ void red_add_v4(float* addr, float a, float b, float c, float d) {
    asm volatile("red.global.add.v4.f32 [%0], {%1,%2,%3,%4};"
                 :: "l"(addr), "f"(a), "f"(b), "f"(c), "f"(d) : "memory");
}
__device__ __forceinline__ void red_add_f32(float* addr, float a) {
    asm volatile("red.global.add.f32 [%0], %1;" :: "l"(addr), "f"(a) : "memory");
}

// ---------------------------------------------------------------------------
// Zero the accumulation buffers (graph replays must re-zero every launch)
// ---------------------------------------------------------------------------
__global__ void zero_kernel() {
    int i = blockIdx.x * blockDim.x + threadIdx.x;
    float4 z = make_float4(0.f, 0.f, 0.f, 0.f);
    if (i < NMAX * 3) ((float4*)g_h1)[i] = z;   // NMAX*12 floats
    if (i < NMAX * 7) ((float4*)g_h2)[i] = z;   // NMAX*28 floats
}

// ---------------------------------------------------------------------------
// xl[n,i] = sum_j gauges[n,j,i] * x[n,j]   (project onto gauge columns)
// ---------------------------------------------------------------------------
__global__ void xl_kernel(const float* __restrict__ x,
                          const float* __restrict__ g, int N) {
    int n = blockIdx.x * blockDim.x + threadIdx.x;
    if (n >= N) return;
    float x0 = x[n * 3 + 0], x1 = x[n * 3 + 1], x2 = x[n * 3 + 2];
    const float* G = g + n * 9;
    float o0 = x0 * G[0] + x1 * G[3] + x2 * G[6];
    float o1 = x0 * G[1] + x1 * G[4] + x2 * G[7];
    float o2 = x0 * G[2] + x1 * G[5] + x2 * G[8];
    ((float4*)g_xl)[n] = make_float4(o0, o1, o2, 0.f);
}

// ---------------------------------------------------------------------------
// conv1: h1[dst, c*3+k] += K[k,e] * xl[src, c]   (9 values/edge -> 2 v4 + 1 scalar)
// edge_index is int32 (JAX silently downcasts int64 without x64 enabled)
// ---------------------------------------------------------------------------
__global__ void conv1_kernel(const int* __restrict__ ei,
                             const float* __restrict__ K, int E) {
    int e = blockIdx.x * blockDim.x + threadIdx.x;
    if (e >= E) return;
    int s = ei[e];
    int d = ei[E + e];
    float k0 = K[e], k1 = K[E + e], k2 = K[2 * E + e];
    float4 xv = ((const float4*)g_xl)[s];
    float* row = g_h1 + d * 12;
    red_add_v4(row,     k0 * xv.x, k1 * xv.x, k2 * xv.x, k0 * xv.y);
    red_add_v4(row + 4, k1 * xv.y, k2 * xv.y, k0 * xv.z, k1 * xv.z);
    red_add_f32(row + 8, k2 * xv.z);
}

// ---------------------------------------------------------------------------
// conv2: h2[dst, c*3+k] += K[k,e] * h1[src, c]   c in [0,9) -> 27 values/edge -> 7 v4
// ---------------------------------------------------------------------------
__global__ void conv2_kernel(const int* __restrict__ ei,
                             const float* __restrict__ K, int E) {
    int e = blockIdx.x * blockDim.x + threadIdx.x;
    if (e >= E) return;
    int s = ei[e];
    int d = ei[E + e];
    float k0 = K[e], k1 = K[E + e], k2 = K[2 * E + e];
    const float4* h1r = (const float4*)(g_h1 + s * 12);
    float4 A = h1r[0], B = h1r[1], C = h1r[2];
    float a[9] = {A.x, A.y, A.z, A.w, B.x, B.y, B.z, B.w, C.x};
    float v[28];
#pragma unroll
    for (int c = 0; c < 9; c++) {
        v[3 * c + 0] = k0 * a[c];
        v[3 * c + 1] = k1 * a[c];
        v[3 * c + 2] = k2 * a[c];
    }
    v[27] = 0.f;
    float* row = g_h2 + d * 28;
#pragma unroll
    for (int q = 0; q < 7; q++)
        red_add_v4(row + 4 * q, v[4 * q], v[4 * q + 1], v[4 * q + 2], v[4 * q + 3]);
}

// ---------------------------------------------------------------------------
// MLP: feats[39] = [xl(3) | h1(9) | h2(27)];  relu(feats@W1+b1)@W2+b2 -> out[64]
// One block = NT=32 nodes, 256 threads.
//   layer1: thread t owns hidden unit t, accumulates all 32 nodes in registers.
//   layer2: thread computes 4 nodes x 2 outputs register tile.
// ---------------------------------------------------------------------------
__global__ __launch_bounds__(256) void mlp_kernel(
    const float* __restrict__ W1, const float* __restrict__ b1,
    const float* __restrict__ W2, const float* __restrict__ b2,
    float* __restrict__ out, int N) {
    __shared__ float sh_feats[39 * NT];        // [j][n], rows of 32 (128B)
    __shared__ float sh_hmid[HID * 36];        // [h][n], stride 36 (144B, 16B-aligned)

    int t = threadIdx.x;
    int node0 = blockIdx.x * NT;

    // --- load feats (transposed) ---
    {
        int n = t & (NT - 1);
        int node = node0 + n;
        bool valid = node < N;
        for (int j = t >> 5; j < 39; j += 8) {
            float v = 0.f;
            if (valid) {
                if (j < 3)       v = g_xl[node * 4 + j];
                else if (j < 12) v = g_h1[node * 12 + (j - 3)];
                else             v = g_h2[node * 28 + (j - 12)];
            }
            sh_feats[j * NT + n] = v;
        }
    }
    __syncthreads();

    // --- layer 1: hid[t][n] for n in [0,32) ---
    float acc[NT];
#pragma unroll
    for (int n = 0; n < NT; n++) acc[n] = 0.f;

    for (int j = 0; j < 39; j++) {
        float w = __ldg(W1 + j * HID + t);
        const float4* f4 = (const float4*)(sh_feats + j * NT);
#pragma unroll
        for (int q = 0; q < NT / 4; q++) {
            float4 f = f4[q];
            acc[4 * q + 0] += f.x * w;
            acc[4 * q + 1] += f.y * w;
            acc[4 * q + 2] += f.z * w;
            acc[4 * q + 3] += f.w * w;
        }
    }
    {
        float bb = __ldg(b1 + t);
        float* hr = sh_hmid + t * 36;
#pragma unroll
        for (int n = 0; n < NT; n++) hr[n] = fmaxf(acc[n] + bb, 0.f);
    }
    __syncthreads();

    // --- layer 2: 4 nodes x 2 outputs per thread ---
    int ng = t & 7;           // node group: nodes 4*ng .. 4*ng+3
    int og = t >> 3;          // output pair: o = 2*og, 2*og+1
    int nb = 4 * ng;
    int o0 = 2 * og;
    float a00 = 0, a01 = 0, a10 = 0, a11 = 0, a20 = 0, a21 = 0, a30 = 0, a31 = 0;
#pragma unroll 4
    for (int h = 0; h < HID; h++) {
        float4 hm = *(const float4*)(sh_hmid + h * 36 + nb);
        float2 w = __ldg((const float2*)(W2 + h * OUT + o0));
        a00 += hm.x * w.x; a01 += hm.x * w.y;
        a10 += hm.y * w.x; a11 += hm.y * w.y;
        a20 += hm.z * w.x; a21 += hm.z * w.y;
        a30 += hm.w * w.x; a31 += hm.w * w.y;
    }
    float bo0 = __ldg(b2 + o0), bo1 = __ldg(b2 + o0 + 1);
    int node = node0 + nb;
    if (node + 0 < N) *(float2*)(out + (node + 0) * OUT + o0) = make_float2(a00 + bo0, a01 + bo1);
    if (node + 1 < N) *(float2*)(out + (node + 1) * OUT + o0) = make_float2(a10 + bo0, a11 + bo1);
    if (node + 2 < N) *(float2*)(out + (node + 2) * OUT + o0) = make_float2(a20 + bo0, a21 + bo1);
    if (node + 3 < N) *(float2*)(out + (node + 3) * OUT + o0) = make_float2(a30 + bo0, a31 + bo1);
}

// ---------------------------------------------------------------------------
// Launch
// Inputs (metadata order): x, gauges, kernel_vals, W1, b1, W2, b2, edge_index
// ---------------------------------------------------------------------------
extern "C" void kernel_launch(void* const* d_in, const int* in_sizes, int n_in,
                              void* d_out, int out_size) {
    const float* x      = (const float*)d_in[0];
    const float* gauges = (const float*)d_in[1];
    const float* kvals  = (const float*)d_in[2];
    const float* W1     = (const float*)d_in[3];
    const float* b1     = (const float*)d_in[4];
    const float* W2     = (const float*)d_in[5];
    const float* b2     = (const float*)d_in[6];
    const int*   ei     = (const int*)d_in[7];   // int32! (JAX x64 disabled)
    float* out = (float*)d_out;

    int N = in_sizes[0] / 3;       // 100000
    int E = in_sizes[2] / 3;       // 6400000

    // zero accumulators (covers NMAX*7 float4 of g_h2 and NMAX*3 of g_h1)
    zero_kernel<<<(NMAX * 7 + 255) / 256, 256>>>();
    xl_kernel<<<(N + 255) / 256, 256>>>(x, gauges, N);
    conv1_kernel<<<(E + 255) / 256, 256>>>(ei, kvals, E);
    conv2_kernel<<<(E + 255) / 256, 256>>>(ei, kvals, E);
    mlp_kernel<<<(N + NT - 1) / NT, 256>>>(W1, b1, W2, b2, out, N);
}